// round 16
// baseline (speedup 1.0000x reference)
#include <cuda_runtime.h>
#include <cuda_fp16.h>
#include <mma.h>
#include <math.h>
#include <cstdint>

using namespace nvcuda;

#define B_   2
#define S_   2048
#define H_   1024
#define NH_  16
#define HD_  64
#define MR_  (B_ * S_)
#define ATTN_SCALE 0.125f

// ---------------- scratch (half everywhere on the MMA paths) -----------------
__device__ __half g_x_h[MR_ * H_];           // fp16 x            [M][K]
__device__ __half g_wqkv_h[H_ * 3 * H_];     // fp16 w_qkv        [K][N]
__device__ __half g_wout_h[H_ * H_];         // fp16 w_out        [K][N]
__device__ __half g_q[B_ * NH_ * S_ * HD_];  // (b,h,s,d) q pre-scaled
__device__ __half g_k[B_ * NH_ * S_ * HD_];
__device__ __half g_v[B_ * NH_ * S_ * HD_];
__device__ __half g_att[MR_ * H_];           // (b,s,H)

// ---------------- cp.async helpers ------------------------------------------
__device__ __forceinline__ unsigned smem_u32(const void* p) {
    return (unsigned)__cvta_generic_to_shared(p);
}
#define CP_ASYNC16(dst_u32, src_ptr) \
    asm volatile("cp.async.cg.shared.global [%0], [%1], 16;\n" :: "r"(dst_u32), "l"(src_ptr))
#define CP_COMMIT() asm volatile("cp.async.commit_group;\n" ::)
#define CP_WAIT(N)  asm volatile("cp.async.wait_group %0;\n" :: "n"(N))

// ---------------- prep: fused fp32 -> fp16 conversion ------------------------
#define N4_X  (MR_ * H_ / 4)
#define N4_WQ (H_ * 3 * H_ / 4)
#define N4_WO (H_ * H_ / 4)
#define N4_TOTAL (N4_X + N4_WQ + N4_WO)

__global__ void tohalf_all_kernel(const float4* __restrict__ x,
                                  const float4* __restrict__ wqkv,
                                  const float4* __restrict__ wout)
{
    int i = blockIdx.x * blockDim.x + threadIdx.x;
    const float4* src;
    __half2* dst;
    int j;
    if (i < N4_X)              { src = x;    dst = (__half2*)g_x_h;    j = i; }
    else if (i < N4_X + N4_WQ) { src = wqkv; dst = (__half2*)g_wqkv_h; j = i - N4_X; }
    else if (i < N4_TOTAL)     { src = wout; dst = (__half2*)g_wout_h; j = i - N4_X - N4_WQ; }
    else return;
    float4 v = src[j];
    dst[2 * j]     = __floats2half2_rn(v.x, v.y);
    dst[2 * j + 1] = __floats2half2_rn(v.z, v.w);
}

// ---------------- fp16 wmma GEMM (unchanged from R15: BK=64) -----------------
#define BM 128
#define BN 128
#define BK 64
#define LDA_H 80
#define LDB_H 144
#define A_STAGE_H (BM * LDA_H)
#define B_STAGE_H (BK * LDB_H)
#define GEMM_SMEM ((2 * A_STAGE_H + 2 * B_STAGE_H) * 2)

template <int EPI>
__global__ __launch_bounds__(128) void gemm_fp16_kernel(
    const float* __restrict__ bias, float* __restrict__ C,
    int M, int N, int K)
{
    const __half* A  = (EPI == 1) ? (const __half*)g_att    : (const __half*)g_x_h;
    const __half* Bw = (EPI == 1) ? (const __half*)g_wout_h : (const __half*)g_wqkv_h;

    extern __shared__ __half smh[];
    __half* As = smh;
    __half* Bs = smh + 2 * A_STAGE_H;

    const int bm   = blockIdx.y * BM;
    const int bn   = blockIdx.x * BN;
    const int tid  = threadIdx.x;
    const int warp = tid >> 5;
    const int lane = tid & 31;
    const int wm   = warp >> 1;
    const int wn   = warp & 1;

    wmma::fragment<wmma::accumulator, 16, 16, 16, float> acc[4][4];
#pragma unroll
    for (int i = 0; i < 4; i++)
#pragma unroll
        for (int j = 0; j < 4; j++) wmma::fill_fragment(acc[i][j], 0.0f);

    const int NIT = K / BK;

    auto load_stage = [&](int st, int k0) {
#pragma unroll
        for (int it = 0; it < 8; it++) {
            int idx = tid + it * 128;
            int r   = idx >> 3;
            int c8  = (idx & 7) << 3;
            CP_ASYNC16(smem_u32(&As[st * A_STAGE_H + r * LDA_H + c8]),
                       &A[(size_t)(bm + r) * K + k0 + c8]);
        }
#pragma unroll
        for (int it = 0; it < 8; it++) {
            int idx = tid + it * 128;
            int r   = idx >> 4;
            int c8  = (idx & 15) << 3;
            CP_ASYNC16(smem_u32(&Bs[st * B_STAGE_H + r * LDB_H + c8]),
                       &Bw[(size_t)(k0 + r) * N + bn + c8]);
        }
    };

    load_stage(0, 0);
    CP_COMMIT();

    for (int it = 0; it < NIT; it++) {
        if (it + 1 < NIT) {
            load_stage((it + 1) & 1, (it + 1) * BK);
            CP_COMMIT();
            CP_WAIT(1);
        } else {
            CP_WAIT(0);
        }
        __syncthreads();

        const __half* Ac = &As[(it & 1) * A_STAGE_H];
        const __half* Bc = &Bs[(it & 1) * B_STAGE_H];
#pragma unroll
        for (int kk = 0; kk < BK / 16; kk++) {
            wmma::fragment<wmma::matrix_a, 16, 16, 16, __half, wmma::row_major> af[4];
            wmma::fragment<wmma::matrix_b, 16, 16, 16, __half, wmma::row_major> bf[4];
#pragma unroll
            for (int i = 0; i < 4; i++)
                wmma::load_matrix_sync(af[i], &Ac[(wm * 64 + i * 16) * LDA_H + kk * 16], LDA_H);
#pragma unroll
            for (int j = 0; j < 4; j++)
                wmma::load_matrix_sync(bf[j], &Bc[(kk * 16) * LDB_H + wn * 64 + j * 16], LDB_H);
#pragma unroll
            for (int i = 0; i < 4; i++)
#pragma unroll
                for (int j = 0; j < 4; j++)
                    wmma::mma_sync(acc[i][j], af[i], bf[j], acc[i][j]);
        }
        __syncthreads();
    }

    float* scr = (float*)smh + warp * 16 * 20;
#pragma unroll
    for (int i = 0; i < 4; i++) {
#pragma unroll
        for (int j = 0; j < 4; j++) {
            wmma::store_matrix_sync(scr, acc[i][j], 20, wmma::mem_row_major);
            __syncwarp();
#pragma unroll
            for (int e = 0; e < 8; e++) {
                int idx = lane + e * 32;
                int rr = idx >> 4, cc = idx & 15;
                int m = bm + wm * 64 + i * 16 + rr;
                int n = bn + wn * 64 + j * 16 + cc;
                float val = scr[rr * 20 + cc] + bias[n];
                if (EPI == 0) {
                    int which = n >> 10;           // 0=q 1=k 2=v
                    int hn = n & (H_ - 1);
                    int h  = hn >> 6;
                    int d  = hn & (HD_ - 1);
                    int bb = m >> 11;
                    int s  = m & (S_ - 1);
                    if (which == 0) val *= ATTN_SCALE;
                    size_t dst = ((size_t)(bb * NH_ + h) * S_ + s) * HD_ + d;
                    __half* T = (which == 0) ? g_q : (which == 1) ? g_k : g_v;
                    T[dst] = __float2half_rn(val);
                } else {
                    C[(size_t)m * N + n] = val;
                }
            }
            __syncwarp();
        }
    }
}

// ---------------- fp16 wmma attention: 128-row Q tiles, warp-private ---------
// 8 warps; warp w owns rows w*16..w*16+16 x full 64-key width (private P strip,
// syncwarp-only softmax). Only block barrier = KV double-buffer guard [A].
// Mask (allow j >= i): per warp per tile: fully-masked -> skip; diagonal ->
// masked scalar pass; else branch-free fast path. l kept in registers.
#define QROWS 128
#define LDS_KV 80
#define KV_ST (64 * LDS_KV)              // halves per stage per tensor
#define PH_STRIDE (16 * LDS_KV)          // per-warp P strip (halves)
#define LDS_OF 72
#define ATTN_SMEM ((4 * KV_ST + 8 * PH_STRIDE) * 2 + 64)   // ~61.5 KB

__global__ __launch_bounds__(256) void attn_fp16_kernel()
{
    extern __shared__ __half smh[];
    __half* Ks = smh;                        // [2][64][LDS_KV]
    __half* Vs = smh + 2 * KV_ST;            // [2][64][LDS_KV]
    __half* Pw = smh + 4 * KV_ST;            // [8][16][LDS_KV] warp strips (Q then P)
    float*  Of = (float*)smh;                // O staging after loop (Ks/Vs dead)

    const int qt = blockIdx.x;               // 0..15 (128-row Q tiles)
    const int bh = blockIdx.y;
    const __half* Qb = g_q + (size_t)bh * S_ * HD_;
    const __half* Kb = g_k + (size_t)bh * S_ * HD_;
    const __half* Vb = g_v + (size_t)bh * S_ * HD_;

    const int tid  = threadIdx.x;
    const int warp = tid >> 5;
    const int lane = tid & 31;
    __half* Ph = Pw + warp * PH_STRIDE;      // this warp's 16x64 strip
    const int wrow0 = qt * QROWS + warp * 16;    // first global row of strip
    const int lrow  = lane >> 1;                 // 0..15 strip row
    const int lc0   = (lane & 1) * 32;           // col half base

    auto load_kv = [&](int st, int kt) {
#pragma unroll
        for (int it = 0; it < 2; it++) {
            int idx = tid + it * 256;        // 0..511
            int r   = idx >> 3;
            int c8  = (idx & 7) << 3;
            size_t src = (size_t)(kt * 64 + r) * HD_ + c8;
            CP_ASYNC16(smem_u32(&Ks[st * KV_ST + r * LDS_KV + c8]), &Kb[src]);
            CP_ASYNC16(smem_u32(&Vs[st * KV_ST + r * LDS_KV + c8]), &Vb[src]);
        }
    };

    const int kt0 = qt * 2;
    const int nkt = S_ / 64 - kt0;           // >= 2

    load_kv(0, kt0);
    CP_COMMIT();

    // stage Q rows qt*128..+128 into the warp strips (Pw[r*LDS_KV] since
    // PH_STRIDE = 16*LDS_KV makes strips contiguous by row)
#pragma unroll
    for (int it = 0; it < 4; it++) {
        int idx = tid + it * 256;            // 0..1023
        int r   = idx >> 3;
        int c8  = (idx & 7) << 3;
        *reinterpret_cast<uint4*>(&Pw[r * LDS_KV + c8]) =
            *reinterpret_cast<const uint4*>(&Qb[(size_t)(qt * QROWS + r) * HD_ + c8]);
    }
    __syncthreads();

    wmma::fragment<wmma::matrix_a, 16, 16, 16, __half, wmma::row_major> qf[4];
#pragma unroll
    for (int kk = 0; kk < 4; kk++)
        wmma::load_matrix_sync(qf[kk], &Ph[kk * 16], LDS_KV);
    // Ph reuse below is warp-local; qf loads precede first store in program order

    wmma::fragment<wmma::accumulator, 16, 16, 16, float> o_acc[4];
#pragma unroll
    for (int j = 0; j < 4; j++) wmma::fill_fragment(o_acc[j], 0.0f);
    float lsum = 0.0f;                        // full row sum for row lrow

    for (int i = 0; i < nkt; i++) {
        const int kt = kt0 + i;
        CP_WAIT(0);
        __syncthreads();                      // [A] KV stage i visible; other slot free
        if (i + 1 < nkt) {
            load_kv((i + 1) & 1, kt + 1);     // overlaps compute
            CP_COMMIT();
        }
        const __half* Kc = &Ks[(i & 1) * KV_ST];
        const __half* Vc = &Vs[(i & 1) * KV_ST];

        if (kt * 64 + 63 < wrow0) continue;   // tile fully masked for this warp

        // S = Q @ K^T  (16 x 64)
        wmma::fragment<wmma::accumulator, 16, 16, 16, float> s_acc[4];
#pragma unroll
        for (int j = 0; j < 4; j++) wmma::fill_fragment(s_acc[j], 0.0f);
#pragma unroll
        for (int kk = 0; kk < 4; kk++) {
#pragma unroll
            for (int j = 0; j < 4; j++) {
                wmma::fragment<wmma::matrix_b, 16, 16, 16, __half, wmma::col_major> kf;
                wmma::load_matrix_sync(kf, &Kc[(j * 16) * LDS_KV + kk * 16], LDS_KV);
                wmma::mma_sync(s_acc[j], qf[kk], kf, s_acc[j]);
            }
        }

        // exp + fp16 convert in-register; store P to own strip
#pragma unroll
        for (int j = 0; j < 4; j++) {
            wmma::fragment<wmma::accumulator, 16, 16, 16, __half> p_h;
#pragma unroll
            for (int t = 0; t < s_acc[j].num_elements; t++)
                p_h.x[t] = __float2half_rn(__expf(s_acc[j].x[t]));
            wmma::store_matrix_sync(&Ph[j * 16], p_h, LDS_KV, wmma::mem_row_major);
        }
        __syncwarp();                          // P strip visible warp-wide

        if (kt * 64 < wrow0 + 16) {
            // diagonal tile for this warp: zero masked entries + sum
            int grow = wrow0 + lrow;
            int gc0  = kt * 64 + lc0;
            float part = 0.0f;
#pragma unroll
            for (int c = 0; c < 32; c++) {
                __half hp = Ph[lrow * LDS_KV + lc0 + c];
                if (gc0 + c < grow) {
                    hp = __ushort_as_half((unsigned short)0);
                    Ph[lrow * LDS_KV + lc0 + c] = hp;
                }
                part += __half2float(hp);
            }
            part += __shfl_xor_sync(0xffffffffu, part, 1);
            lsum += part;
            __syncwarp();                      // masked P visible before PV
        } else {
            // fast path: read-only row sums (concurrent with PV loads)
            float part = 0.0f;
            const __half2* pp = (const __half2*)&Ph[lrow * LDS_KV + lc0];
#pragma unroll
            for (int c = 0; c < 16; c++) {
                float2 f = __half22float2(pp[c]);
                part += f.x + f.y;
            }
            part += __shfl_xor_sync(0xffffffffu, part, 1);
            lsum += part;
        }

        // O += P @ V  (16 x 64)
#pragma unroll
        for (int kk = 0; kk < 4; kk++) {
            wmma::fragment<wmma::matrix_a, 16, 16, 16, __half, wmma::row_major> pf;
            wmma::load_matrix_sync(pf, &Ph[kk * 16], LDS_KV);
#pragma unroll
            for (int j = 0; j < 4; j++) {
                wmma::fragment<wmma::matrix_b, 16, 16, 16, __half, wmma::row_major> vf;
                wmma::load_matrix_sync(vf, &Vc[(kk * 16) * LDS_KV + j * 16], LDS_KV);
                wmma::mma_sync(o_acc[j], pf, vf, o_acc[j]);
            }
        }
        __syncwarp();                          // PV reads done before next P store
    }

    __syncthreads();   // all warps done with Ks/Vs -> reuse as float O staging
    float* Ow = Of + warp * 16 * LDS_OF;
#pragma unroll
    for (int j = 0; j < 4; j++)
        wmma::store_matrix_sync(&Ow[j * 16], o_acc[j], LDS_OF, wmma::mem_row_major);
    __syncwarp();
    {
        int grow = wrow0 + lrow;
        int bb = bh >> 4, h = bh & 15;
        float inv_l = 1.0f / lsum;             // lsum = full row sum (shfl-combined)
        size_t base = ((size_t)bb * S_ + grow) * H_ + h * HD_ + lc0;
#pragma unroll
        for (int c = 0; c < 32; c++)
            g_att[base + c] = __float2half_rn(Ow[lrow * LDS_OF + lc0 + c] * inv_l);
    }
}

// ---------------- launch -----------------------------------------------------
extern "C" void kernel_launch(void* const* d_in, const int* in_sizes, int n_in,
                              void* d_out, int out_size)
{
    const float* x     = (const float*)d_in[0];
    const float* w_qkv = (const float*)d_in[1];
    const float* b_qkv = (const float*)d_in[2];
    const float* w_out = (const float*)d_in[3];
    const float* b_out = (const float*)d_in[4];
    float* out = (float*)d_out;

    cudaFuncSetAttribute(gemm_fp16_kernel<0>,
                         cudaFuncAttributeMaxDynamicSharedMemorySize, GEMM_SMEM);
    cudaFuncSetAttribute(gemm_fp16_kernel<1>,
                         cudaFuncAttributeMaxDynamicSharedMemorySize, GEMM_SMEM);
    cudaFuncSetAttribute(attn_fp16_kernel,
                         cudaFuncAttributeMaxDynamicSharedMemorySize, ATTN_SMEM);

    tohalf_all_kernel<<<(N4_TOTAL + 255) / 256, 256>>>(
        (const float4*)x, (const float4*)w_qkv, (const float4*)w_out);

    dim3 g1((3 * H_) / BN, MR_ / BM);
    gemm_fp16_kernel<0><<<g1, 128, GEMM_SMEM>>>(b_qkv, nullptr, MR_, 3 * H_, H_);

    dim3 g2(S_ / QROWS, B_ * NH_);
    attn_fp16_kernel<<<g2, 256, ATTN_SMEM>>>();

    dim3 g3(H_ / BN, MR_ / BM);
    gemm_fp16_kernel<1><<<g3, 128, GEMM_SMEM>>>(b_out, out, MR_, H_, H_);
}